// round 9
// baseline (speedup 1.0000x reference)
#include <cuda_runtime.h>
#include <cuda_bf16.h>
#include <cstdint>

// EdgeConvE: out[v,h] = sum_w A[v,w] * relu(S[v,h] + T[w,h] + sum_e E[v,w,e]*We[e,h])
// N=1024, F=32, E_ATTR=8, H=64.
// R9 = R8 + ONE change: the S-broadcast add is folded into a rank-1 tf32 MMA
// (A=ones in k-slot0, B=S in k-slot0, C=Tf frag), deleting 32 FADD/wt from the
// fma pipe and 24 instr/wt from issue.
//   prep_st  = R5/R7 version                      ~5 us
//   edge_main = R8 loop + rank-1 S MMA            (16.3 -> ~12.5 us predicted)
//   combine  = R3 separate kernel                 ~2.5 us

#define N_NODES 1024
#define F_NODE  32
#define E_ATTR  8
#define H_OUT   64

__device__ __forceinline__ uint32_t to_tf32(float f) {
    uint32_t u; asm("cvt.rna.tf32.f32 %0, %1;" : "=r"(u) : "f"(f)); return u;
}

// ---------- scratch ----------
__device__ float  g_S [N_NODES * H_OUT];             // 256 KB: S[v,h]=X@(Ws-Wd)+b
__device__ float4 g_Tf[(N_NODES / 16) * 8 * 32];     // 256 KB: T in MMA-C frag layout
__device__ float  g_part[2][N_NODES * H_OUT];        // 512 KB: per-half partials

// ---------- kernel 1: S + fragged T ----------
// grid 256, block 256: 4 v per block, one (vl,h) per thread.
__global__ void __launch_bounds__(256)
prep_st(const float* __restrict__ X, const float* __restrict__ W,
        const float* __restrict__ b) {
    __shared__ float ws[2 * F_NODE * H_OUT];   // 16 KB (rows 0..63 of W)
    __shared__ float xs[4][F_NODE];
    const int tid = threadIdx.x;
    const int v0  = blockIdx.x * 4;

    const float4* W4 = reinterpret_cast<const float4*>(W);
    float4* ws4 = reinterpret_cast<float4*>(ws);
#pragma unroll
    for (int i = 0; i < 4; i++) ws4[tid + 256 * i] = W4[tid + 256 * i];
    if (tid < 32)
        reinterpret_cast<float4*>(xs)[tid] =
            reinterpret_cast<const float4*>(X + v0 * F_NODE)[tid];
    __syncthreads();

    const int h  = tid & 63;
    const int vl = tid >> 6;
    float s = __ldg(&b[h]), t = 0.0f;
#pragma unroll
    for (int f = 0; f < F_NODE; f++) {
        float x  = xs[vl][f];
        float wv = ws[f * H_OUT + h];
        float wd = ws[(f + F_NODE) * H_OUT + h];
        s = fmaf(x, wv - wd, s);
        t = fmaf(x, wd, t);
    }
    const int v = v0 + vl;
    g_S[v * H_OUT + h] = s;
    // scatter T into MMA-C frag layout (matches main kernel's read mapping):
    const int wt   = v >> 4;
    const int gid  = v & 7;
    const int rs   = (v >> 3) & 1;
    const int t4   = (h >> 1) & 3;
    const int j    = h >> 3;
    const int elem = (h & 1) + 2 * rs;
    reinterpret_cast<float*>(g_Tf)[(((wt * 8 + j) * 32) + gid * 4 + t4) * 4 + elem] = t;
}

// ---------- kernel 2: main ----------
// Block: 8 warps = 8 v's, all scanning the SAME w-half (T reuse via L1).
// Grid: (1024/8) * 2 halves = 256 blocks.
// K-permutation (A & B consistent): k-slot t4 <-> attr 2t4, slot t4+4 <-> attr 2t4+1.
// S folded in as rank-1 MMA: D1 = ones(k0) @ S(k0) + Tf ; D = E@We + D1.
__global__ void __launch_bounds__(256, 2)
edge_main(const float* __restrict__ E, const int* __restrict__ A,
          const float* __restrict__ W) {
    const int vg   = blockIdx.x >> 1;
    const int half = blockIdx.x & 1;
    const int warp = threadIdx.x >> 5;
    const int lane = threadIdx.x & 31;
    const int gid  = lane >> 2;            // 0..7
    const int t4   = lane & 3;             // 0..3
    const int v    = vg * 8 + warp;

    // B frags (We in tf32), permuted-K rows 2t4 and 2t4+1
    uint32_t bf0[8], bf1[8];
#pragma unroll
    for (int j = 0; j < 8; j++) {
        bf0[j] = to_tf32(W[(2 * F_NODE + 2 * t4)     * H_OUT + j * 8 + gid]);
        bf1[j] = to_tf32(W[(2 * F_NODE + 2 * t4 + 1) * H_OUT + j * 8 + gid]);
    }
    // rank-1 S operands:
    //   A-frag of ones matrix (k-slot 0 only): a0=a1=1 iff t4==0; a2=a3=0
    //   B-frag: S[v, j*8+gid] in k-slot 0 (lanes with t4==0), else 0
    const uint32_t oneA  = to_tf32(t4 == 0 ? 1.0f : 0.0f);
    const uint32_t zeroR = 0;
    uint32_t sb[8];
#pragma unroll
    for (int j = 0; j < 8; j++)
        sb[j] = (t4 == 0) ? to_tf32(g_S[v * H_OUT + j * 8 + gid]) : 0u;

    float acc0[8], acc1[8];
#pragma unroll
    for (int j = 0; j < 8; j++) { acc0[j] = 0.0f; acc1[j] = 0.0f; }

    const float* __restrict__ Ev = E + (size_t)v * (N_NODES * E_ATTR);
    const int*   __restrict__ Av = A + v * N_NODES;
    const float4* __restrict__ Tf = g_Tf;

    const int wt0 = half * 32;
#pragma unroll 2
    for (int wt = wt0; wt < wt0 + 32; wt++) {
        const int r0 = wt * 16 + gid;
        const int r1 = r0 + 8;
        // E A-frag, permuted K: one contiguous LDG.64 per row
        float2 e0 = *(const float2*)&Ev[r0 * E_ATTR + 2 * t4];
        float2 e1 = *(const float2*)&Ev[r1 * E_ATTR + 2 * t4];
        uint32_t a0 = to_tf32(e0.x);
        uint32_t a2 = to_tf32(e0.y);
        uint32_t a1 = to_tf32(e1.x);
        uint32_t a3 = to_tf32(e1.y);
        float aF0 = (float)Av[r0];
        float aF1 = (float)Av[r1];
#pragma unroll
        for (int j = 0; j < 8; j++) {
            float4 c = Tf[(wt * 8 + j) * 32 + lane];   // coalesced 512B/warp
            // MMA2: D1 = ones(k0) @ S(k0) + Tf
            float p0, p1, p2, p3;
            asm("mma.sync.aligned.m16n8k8.row.col.f32.tf32.tf32.f32 "
                "{%0,%1,%2,%3}, {%4,%5,%6,%7}, {%8,%9}, {%10,%11,%12,%13};"
                : "=f"(p0), "=f"(p1), "=f"(p2), "=f"(p3)
                : "r"(oneA), "r"(oneA), "r"(zeroR), "r"(zeroR),
                  "r"(sb[j]), "r"(zeroR),
                  "f"(c.x), "f"(c.y), "f"(c.z), "f"(c.w));
            // MMA1: D = E @ We + D1
            float d0, d1, d2, d3;
            asm("mma.sync.aligned.m16n8k8.row.col.f32.tf32.tf32.f32 "
                "{%0,%1,%2,%3}, {%4,%5,%6,%7}, {%8,%9}, {%10,%11,%12,%13};"
                : "=f"(d0), "=f"(d1), "=f"(d2), "=f"(d3)
                : "r"(a0), "r"(a1), "r"(a2), "r"(a3),
                  "r"(bf0[j]), "r"(bf1[j]),
                  "f"(p0), "f"(p1), "f"(p2), "f"(p3));
            d0 = fmaxf(d0, 0.0f);
            d1 = fmaxf(d1, 0.0f);
            d2 = fmaxf(d2, 0.0f);
            d3 = fmaxf(d3, 0.0f);
            acc0[j] = fmaf(aF0, d0, acc0[j]);
            acc0[j] = fmaf(aF1, d2, acc0[j]);
            acc1[j] = fmaf(aF0, d1, acc1[j]);
            acc1[j] = fmaf(aF1, d3, acc1[j]);
        }
    }

    // reduce across the 8 row-groups (xor over gid bits: lanes 4,8,16)
#pragma unroll
    for (int j = 0; j < 8; j++) {
        float a = acc0[j], bq = acc1[j];
        a  += __shfl_xor_sync(0xffffffffu, a, 4);
        bq += __shfl_xor_sync(0xffffffffu, bq, 4);
        a  += __shfl_xor_sync(0xffffffffu, a, 8);
        bq += __shfl_xor_sync(0xffffffffu, bq, 8);
        a  += __shfl_xor_sync(0xffffffffu, a, 16);
        bq += __shfl_xor_sync(0xffffffffu, bq, 16);
        if (gid == 0)
            *(float2*)&g_part[half][v * H_OUT + j * 8 + 2 * t4] = make_float2(a, bq);
    }
}

// ---------- kernel 3: deterministic combine ----------
__global__ void combine(float* __restrict__ out) {
    const int i = blockIdx.x * 256 + threadIdx.x;
    out[i] = g_part[0][i] + g_part[1][i];
}

// ---------- launch ----------
extern "C" void kernel_launch(void* const* d_in, const int* in_sizes, int n_in,
                              void* d_out, int out_size) {
    const int*   adj = (const int*)d_in[0];       // (1,1024,1024) int32
    const float* X   = (const float*)d_in[1];     // (1,1024,32)
    const float* E   = (const float*)d_in[2];     // (1,1024,1024,8)
    const float* W   = (const float*)d_in[3];     // (72,64)
    const float* b   = (const float*)d_in[4];     // (64,)
    float* out = (float*)d_out;                   // (1,1024,64)

    prep_st<<<N_NODES / 4, 256>>>(X, W, b);
    edge_main<<<(N_NODES / 8) * 2, 256>>>(E, adj, W);
    combine<<<(N_NODES * H_OUT) / 256, 256>>>(out);
}

// round 11
// speedup vs baseline: 1.1415x; 1.1415x over previous
#include <cuda_runtime.h>
#include <cuda_bf16.h>
#include <cstdint>

// EdgeConvE: out[v,h] = sum_w A[v,w] * relu(S[v,h] + T[w,h] + sum_e E[v,w,e]*We[e,h])
// N=1024, F=32, E_ATTR=8, H=64.
// R10 = R8 (best: 27.1us) + ONE change: software prefetch of next-iteration
// E/A values across the j-loop (load->use distance ~10 -> ~110 instr).
//   prep_st  = R5/R7 version                      ~5 us
//   edge_main = R8 loop + E/A prefetch            (16.3 -> ~14 us predicted)
//   combine  = R3 separate kernel                 ~2.5 us

#define N_NODES 1024
#define F_NODE  32
#define E_ATTR  8
#define H_OUT   64

__device__ __forceinline__ uint32_t to_tf32(float f) {
    uint32_t u; asm("cvt.rna.tf32.f32 %0, %1;" : "=r"(u) : "f"(f)); return u;
}

// ---------- scratch ----------
__device__ float  g_S [N_NODES * H_OUT];             // 256 KB: S[v,h]=X@(Ws-Wd)+b
__device__ float4 g_Tf[(N_NODES / 16) * 8 * 32];     // 256 KB: T in MMA-C frag layout
__device__ float  g_part[2][N_NODES * H_OUT];        // 512 KB: per-half partials

// ---------- kernel 1: S + fragged T ----------
// grid 256, block 256: 4 v per block, one (vl,h) per thread.
__global__ void __launch_bounds__(256)
prep_st(const float* __restrict__ X, const float* __restrict__ W,
        const float* __restrict__ b) {
    __shared__ float ws[2 * F_NODE * H_OUT];   // 16 KB (rows 0..63 of W)
    __shared__ float xs[4][F_NODE];
    const int tid = threadIdx.x;
    const int v0  = blockIdx.x * 4;

    const float4* W4 = reinterpret_cast<const float4*>(W);
    float4* ws4 = reinterpret_cast<float4*>(ws);
#pragma unroll
    for (int i = 0; i < 4; i++) ws4[tid + 256 * i] = W4[tid + 256 * i];
    if (tid < 32)
        reinterpret_cast<float4*>(xs)[tid] =
            reinterpret_cast<const float4*>(X + v0 * F_NODE)[tid];
    __syncthreads();

    const int h  = tid & 63;
    const int vl = tid >> 6;
    float s = __ldg(&b[h]), t = 0.0f;
#pragma unroll
    for (int f = 0; f < F_NODE; f++) {
        float x  = xs[vl][f];
        float wv = ws[f * H_OUT + h];
        float wd = ws[(f + F_NODE) * H_OUT + h];
        s = fmaf(x, wv - wd, s);
        t = fmaf(x, wd, t);
    }
    const int v = v0 + vl;
    g_S[v * H_OUT + h] = s;
    // scatter T into MMA-C frag layout (matches main kernel's read mapping):
    const int wt   = v >> 4;
    const int gid  = v & 7;
    const int rs   = (v >> 3) & 1;
    const int t4   = (h >> 1) & 3;
    const int j    = h >> 3;
    const int elem = (h & 1) + 2 * rs;
    reinterpret_cast<float*>(g_Tf)[(((wt * 8 + j) * 32) + gid * 4 + t4) * 4 + elem] = t;
}

// ---------- kernel 2: main (R8 structure + E/A software prefetch) ----------
// Block: 8 warps = 8 v's, all scanning the SAME w-half (T reuse via L1).
// Grid: (1024/8) * 2 halves = 256 blocks.
// K-permutation (A & B consistent): k-slot t4 <-> attr 2t4, slot t4+4 <-> attr 2t4+1.
__global__ void __launch_bounds__(256, 2)
edge_main(const float* __restrict__ E, const int* __restrict__ A,
          const float* __restrict__ W) {
    const int vg   = blockIdx.x >> 1;
    const int half = blockIdx.x & 1;
    const int warp = threadIdx.x >> 5;
    const int lane = threadIdx.x & 31;
    const int gid  = lane >> 2;            // 0..7
    const int t4   = lane & 3;             // 0..3
    const int v    = vg * 8 + warp;

    // B frags (We in tf32), permuted-K rows 2t4 and 2t4+1
    uint32_t bf0[8], bf1[8];
#pragma unroll
    for (int j = 0; j < 8; j++) {
        bf0[j] = to_tf32(W[(2 * F_NODE + 2 * t4)     * H_OUT + j * 8 + gid]);
        bf1[j] = to_tf32(W[(2 * F_NODE + 2 * t4 + 1) * H_OUT + j * 8 + gid]);
    }
    // S pairs for this lane's h columns
    float2 sj[8];
#pragma unroll
    for (int j = 0; j < 8; j++)
        sj[j] = *(const float2*)&g_S[v * H_OUT + j * 8 + 2 * t4];

    float acc0[8], acc1[8];
#pragma unroll
    for (int j = 0; j < 8; j++) { acc0[j] = 0.0f; acc1[j] = 0.0f; }

    const float* __restrict__ Ev = E + (size_t)v * (N_NODES * E_ATTR);
    const int*   __restrict__ Av = A + v * N_NODES;
    const float4* __restrict__ Tf = g_Tf;

    const int wt0 = half * 32;
    // prime the prefetch pipeline
    int r0 = wt0 * 16 + gid;
    int r1 = r0 + 8;
    float2 pe0 = *(const float2*)&Ev[r0 * E_ATTR + 2 * t4];
    float2 pe1 = *(const float2*)&Ev[r1 * E_ATTR + 2 * t4];
    float  pF0 = (float)Av[r0];
    float  pF1 = (float)Av[r1];

#pragma unroll 2
    for (int wt = wt0; wt < wt0 + 32; wt++) {
        // consume current prefetch
        float2 e0 = pe0, e1 = pe1;
        float aF0 = pF0, aF1 = pF1;
        // issue next iteration's loads (clamped; redundant on last iter)
        const int nwt = (wt + 1 < wt0 + 32) ? wt + 1 : wt;
        const int n0 = nwt * 16 + gid;
        const int n1 = n0 + 8;
        pe0 = *(const float2*)&Ev[n0 * E_ATTR + 2 * t4];
        pe1 = *(const float2*)&Ev[n1 * E_ATTR + 2 * t4];
        pF0 = (float)Av[n0];
        pF1 = (float)Av[n1];

        uint32_t a0 = to_tf32(e0.x);   // (row r0, k-slot t4)   = attr 2t4
        uint32_t a2 = to_tf32(e0.y);   // (row r0, k-slot t4+4) = attr 2t4+1
        uint32_t a1 = to_tf32(e1.x);
        uint32_t a3 = to_tf32(e1.y);
#pragma unroll
        for (int j = 0; j < 8; j++) {
            float4 c = Tf[(wt * 8 + j) * 32 + lane];   // coalesced 512B/warp
            float c0 = c.x + sj[j].x;
            float c1 = c.y + sj[j].y;
            float c2 = c.z + sj[j].x;
            float c3 = c.w + sj[j].y;
            float d0, d1, d2, d3;
            asm("mma.sync.aligned.m16n8k8.row.col.f32.tf32.tf32.f32 "
                "{%0,%1,%2,%3}, {%4,%5,%6,%7}, {%8,%9}, {%10,%11,%12,%13};"
                : "=f"(d0), "=f"(d1), "=f"(d2), "=f"(d3)
                : "r"(a0), "r"(a1), "r"(a2), "r"(a3),
                  "r"(bf0[j]), "r"(bf1[j]),
                  "f"(c0), "f"(c1), "f"(c2), "f"(c3));
            d0 = fmaxf(d0, 0.0f);
            d1 = fmaxf(d1, 0.0f);
            d2 = fmaxf(d2, 0.0f);
            d3 = fmaxf(d3, 0.0f);
            acc0[j] = fmaf(aF0, d0, acc0[j]);
            acc0[j] = fmaf(aF1, d2, acc0[j]);
            acc1[j] = fmaf(aF0, d1, acc1[j]);
            acc1[j] = fmaf(aF1, d3, acc1[j]);
        }
    }

    // reduce across the 8 row-groups (xor over gid bits: lanes 4,8,16)
#pragma unroll
    for (int j = 0; j < 8; j++) {
        float a = acc0[j], bq = acc1[j];
        a  += __shfl_xor_sync(0xffffffffu, a, 4);
        bq += __shfl_xor_sync(0xffffffffu, bq, 4);
        a  += __shfl_xor_sync(0xffffffffu, a, 8);
        bq += __shfl_xor_sync(0xffffffffu, bq, 8);
        a  += __shfl_xor_sync(0xffffffffu, a, 16);
        bq += __shfl_xor_sync(0xffffffffu, bq, 16);
        if (gid == 0)
            *(float2*)&g_part[half][v * H_OUT + j * 8 + 2 * t4] = make_float2(a, bq);
    }
}

// ---------- kernel 3: deterministic combine ----------
__global__ void combine(float* __restrict__ out) {
    const int i = blockIdx.x * 256 + threadIdx.x;
    out[i] = g_part[0][i] + g_part[1][i];
}

// ---------- launch ----------
extern "C" void kernel_launch(void* const* d_in, const int* in_sizes, int n_in,
                              void* d_out, int out_size) {
    const int*   adj = (const int*)d_in[0];       // (1,1024,1024) int32
    const float* X   = (const float*)d_in[1];     // (1,1024,32)
    const float* E   = (const float*)d_in[2];     // (1,1024,1024,8)
    const float* W   = (const float*)d_in[3];     // (72,64)
    const float* b   = (const float*)d_in[4];     // (64,)
    float* out = (float*)d_out;                   // (1,1024,64)

    prep_st<<<N_NODES / 4, 256>>>(X, W, b);
    edge_main<<<(N_NODES / 8) * 2, 256>>>(E, adj, W);
    combine<<<(N_NODES * H_OUT) / 256, 256>>>(out);
}